// round 4
// baseline (speedup 1.0000x reference)
#include <cuda_runtime.h>
#include <cstdint>

// LocalExpansion via scatter with 256-bit stores (sm_103a st.global.v8.b32).
// Thread (p, dv8) owns the 32-byte slice dv8 of pixel p's 64-float vector.
// It loads that slice ONCE (256-bit ld), scatters it to the 49 destinations
// q = p - shift(k) at tap k (predicated in-image), and zero-fills its own
// row's taps whose source is out-of-bounds. Coverage exact & disjoint.
//
// B*H = 16, N = 48*48 = 2304, K = 49, D = 64 floats.
// Output row per pixel = 49*64*4 = 12544 B. Tap stride = 256 B.

#define HEIGHT 48
#define WIDTH  48
#define NPIX   (HEIGHT * WIDTH)       // 2304
#define ROWB   12544                  // bytes per output pixel row (49*256)
#define TAPB   256                    // bytes per tap (64 floats)

__device__ __forceinline__ void stg256_cs(void* p, const uint4& a, const uint4& b) {
    asm volatile("st.global.cs.v8.b32 [%0], {%1,%2,%3,%4,%5,%6,%7,%8};"
        :: "l"(p),
           "r"(a.x), "r"(a.y), "r"(a.z), "r"(a.w),
           "r"(b.x), "r"(b.y), "r"(b.z), "r"(b.w)
        : "memory");
}

__device__ __forceinline__ void ldg256(const void* p, uint4& a, uint4& b) {
    asm volatile("ld.global.nc.v8.b32 {%0,%1,%2,%3,%4,%5,%6,%7}, [%8];"
        : "=r"(a.x), "=r"(a.y), "=r"(a.z), "=r"(a.w),
          "=r"(b.x), "=r"(b.y), "=r"(b.z), "=r"(b.w)
        : "l"(p));
}

__global__ void __launch_bounds__(256) local_scatter_v8_kernel(
    const char* __restrict__ in, char* __restrict__ out)
{
    unsigned int t   = blockIdx.x * 256u + threadIdx.x;   // grid sized exactly
    unsigned int dv8 = t & 7u;                            // which 32B slice of the 256B tap
    unsigned int p   = t >> 3;                            // bh*NPIX + s
    unsigned int n   = p % NPIX;
    int y = (int)(n / WIDTH);
    int x = (int)(n % WIDTH);

    uint4 a, b;
    ldg256(in + (size_t)p * TAPB + dv8 * 32u, a, b);      // single 256-bit load

    char* __restrict__ base = out + (size_t)p * ROWB + dv8 * 32u;
    const uint4 z = make_uint4(0u, 0u, 0u, 0u);

    #pragma unroll
    for (int i = 0; i < 7; ++i) {
        const bool src_yok = (unsigned)(y + (i - 3)) < (unsigned)HEIGHT;
        const bool dst_yok = (unsigned)(y - (i - 3)) < (unsigned)HEIGHT;
        #pragma unroll
        for (int j = 0; j < 7; ++j) {
            const int k = i * 7 + j;
            const bool dst_ok = dst_yok && ((unsigned)(x - (j - 3)) < (unsigned)WIDTH);
            const bool src_ok = src_yok && ((unsigned)(x + (j - 3)) < (unsigned)WIDTH);

            // scatter my 32B to pixel q = p - shift(k), tap k (immediate offset)
            const int scat_off = -(((i - 3) * WIDTH) + (j - 3)) * ROWB + k * TAPB;
            if (dst_ok) stg256_cs(base + scat_off, a, b);
            // zero-fill my own row's tap k if its source is out of bounds
            if (!src_ok) stg256_cs(base + k * TAPB, z, z);
        }
    }
}

extern "C" void kernel_launch(void* const* d_in, const int* in_sizes, int n_in,
                              void* d_out, int out_size)
{
    const char* in = (const char*)d_in[0];
    char* out = (char*)d_out;

    // threads = 16 * 2304 * 8 = 294912 = 1152 blocks * 256 (exact, no tail)
    unsigned int nthreads = (unsigned int)(out_size / (8 * 49));
    unsigned int blocks = nthreads / 256u;
    local_scatter_v8_kernel<<<blocks, 256>>>(in, out);
}

// round 5
// speedup vs baseline: 1.0555x; 1.0555x over previous
#include <cuda_runtime.h>
#include <cstdint>

// LocalExpansion, SMEM-staged + bulk async store (sm_103a UBLKCP path).
// Each CTA produces 2 consecutive output pixel-rows (2 * 49 taps * 256 B =
// 25088 B, contiguous in gmem): gathers the 7x7 zero-padded window into SMEM
// (input is L1/L2-hot: per-CTA gmem working set ~14 KB), then issues ONE
// cp.async.bulk shared->global for the whole chunk. Tests whether the bulk
// write path beats the STG drain path at DRAM.
//
// B*H = 16, N = 48*48 = 2304, K = 49, D = 64 floats (= 16 float4).

#define HEIGHT 48
#define WIDTH  48
#define NPIX   (HEIGHT * WIDTH)          // 2304
#define KK     49
#define DVEC   16                        // float4 per tap
#define PIX_PER_CTA 2
#define THREADS 256
#define ELEMS  (PIX_PER_CTA * KK * DVEC) // 1568 float4
#define SMEM_BYTES (ELEMS * 16)          // 25088

__global__ void __launch_bounds__(THREADS) local_expand_bulk_kernel(
    const float4* __restrict__ in, float4* __restrict__ out)
{
    __shared__ alignas(128) float4 tile[ELEMS];

    const unsigned int p0 = blockIdx.x * PIX_PER_CTA;

    #pragma unroll
    for (int it = 0; it < (ELEMS + THREADS - 1) / THREADS; ++it) {
        unsigned int idx = threadIdx.x + it * THREADS;
        if (idx < ELEMS) {
            unsigned int dv = idx & (DVEC - 1);
            unsigned int r  = idx >> 4;          // pp*49 + k
            unsigned int k  = r % KK;
            unsigned int pp = r / KK;
            unsigned int p  = p0 + pp;
            unsigned int n  = p % NPIX;
            int y = (int)(n / WIDTH);
            int x = (int)(n % WIDTH);
            int i = (int)(k / 7);
            int j = (int)(k % 7);
            int sy = y + i - 3;
            int sx = x + j - 3;

            float4 v = make_float4(0.f, 0.f, 0.f, 0.f);
            if ((unsigned)sy < (unsigned)HEIGHT && (unsigned)sx < (unsigned)WIDTH) {
                // (p - n) = bh * NPIX
                v = __ldg(in + ((size_t)(p - n) + (unsigned)(sy * WIDTH + sx)) * DVEC + dv);
            }
            tile[idx] = v;
        }
    }

    __syncthreads();
    asm volatile("fence.proxy.async.shared::cta;" ::: "memory");

    if (threadIdx.x == 0) {
        uint32_t saddr;
        asm("{ .reg .u64 t; cvta.to.shared.u64 t, %1; cvt.u32.u64 %0, t; }"
            : "=r"(saddr) : "l"(tile));
        const float4* dst = out + (size_t)p0 * (KK * DVEC);
        asm volatile("cp.async.bulk.global.shared::cta.bulk_group [%0], [%1], %2;"
            :: "l"(dst), "r"(saddr), "r"((unsigned)SMEM_BYTES) : "memory");
        asm volatile("cp.async.bulk.commit_group;" ::: "memory");
        // smem must stay valid until the bulk engine has READ it
        asm volatile("cp.async.bulk.wait_group.read 0;" ::: "memory");
    }
}

extern "C" void kernel_launch(void* const* d_in, const int* in_sizes, int n_in,
                              void* d_out, int out_size)
{
    const float4* in = (const float4*)d_in[0];
    float4* out = (float4*)d_out;

    // pixels total = out floats / (49*64) = 36864 ; CTAs = /2 = 18432
    unsigned int npix_total = (unsigned int)(out_size / (KK * 64));
    unsigned int blocks = npix_total / PIX_PER_CTA;
    local_expand_bulk_kernel<<<blocks, THREADS>>>(in, out);
}